// round 11
// baseline (speedup 1.0000x reference)
#include <cuda_runtime.h>
#include <cuda_fp16.h>
#include <cstdint>
#include <math.h>

// MoE FFN: router top-2 -> grouped HMMA GEMM (in-kernel fp32->fp16 hi/lo split,
// 2-term mma.sync: Ah*Bh + Al*Bh) -> combine.
// R11 = R9 + cp.async raw-fp32 B staging (latency hidden under MMA),
// SMEM 46KB/CTA so 2 CTAs/SM is preserved.

#define MAXE      16
#define CAP_ROWS  8192
#define CAP_H     4096
#define CAP_D     1024

__device__ int   g_cnt[MAXE];
__device__ int   g_off[MAXE];
__device__ int   g_cur[MAXE];
__device__ int   g_rows[CAP_ROWS];
__device__ int   g_tki[CAP_ROWS];
__device__ float g_tkw[CAP_ROWS];
__device__ float g_hidden[(size_t)CAP_ROWS * CAP_H];  // 128 MB
__device__ float g_ybuf[(size_t)CAP_ROWS * CAP_D];    // 32 MB

// ================================================================ helpers
__device__ __forceinline__ void mma16816(float* c, const uint32_t* a,
                                         const uint32_t* b) {
    asm volatile(
        "mma.sync.aligned.m16n8k16.row.col.f32.f16.f16.f32 "
        "{%0,%1,%2,%3}, {%4,%5,%6,%7}, {%8,%9}, {%0,%1,%2,%3};"
        : "+f"(c[0]), "+f"(c[1]), "+f"(c[2]), "+f"(c[3])
        : "r"(a[0]), "r"(a[1]), "r"(a[2]), "r"(a[3]), "r"(b[0]), "r"(b[1]));
}
__device__ __forceinline__ uint32_t packh(__half a, __half b) {
    return (uint32_t)__half_as_ushort(a) | ((uint32_t)__half_as_ushort(b) << 16);
}
__device__ __forceinline__ float gelu_exact(float v) {
    return 0.5f * v * (1.0f + erff(v * 0.70710678118654752f));
}
__device__ __forceinline__ uint32_t smem_u32(const void* p) {
    uint32_t a;
    asm("{ .reg .u64 t; cvta.to.shared.u64 t, %1; cvt.u32.u64 %0, t; }"
        : "=r"(a) : "l"(p));
    return a;
}
__device__ __forceinline__ void cpa16(uint32_t s, const void* g) {
    asm volatile("cp.async.cg.shared.global [%0], [%1], 16;\n"
                 :: "r"(s), "l"(g) : "memory");
}
#define CP_COMMIT() asm volatile("cp.async.commit_group;\n" ::: "memory")
#define CP_WAIT0()  asm volatile("cp.async.wait_group 0;\n" ::: "memory")

// ================================================================ router chain
__global__ void init_kernel(int E) {
    if (threadIdx.x < E) g_cnt[threadIdx.x] = 0;
}

__global__ __launch_bounds__(128) void router_kernel(
    const float* __restrict__ x, const float* __restrict__ gw, int D, int E)
{
    int n = blockIdx.x, t = threadIdx.x;
    float acc[MAXE];
    #pragma unroll
    for (int e = 0; e < MAXE; e++) acc[e] = 0.f;
    const float* xr = x + (size_t)n * D;
    for (int i = t; i < D; i += 128) {
        float xv = xr[i];
        const float* g = gw + (size_t)i * E;
        for (int e = 0; e < E; e++) acc[e] += xv * g[e];
    }
    for (int e = 0; e < E; e++)
        for (int o = 16; o > 0; o >>= 1)
            acc[e] += __shfl_down_sync(0xffffffffu, acc[e], o);
    __shared__ float sred[4][MAXE];
    int warp = t >> 5, lane = t & 31;
    if (lane == 0)
        for (int e = 0; e < E; e++) sred[warp][e] = acc[e];
    __syncthreads();
    if (t == 0) {
        float l[MAXE];
        for (int e = 0; e < E; e++)
            l[e] = sred[0][e] + sred[1][e] + sred[2][e] + sred[3][e];
        int i0 = 0;
        for (int e = 1; e < E; e++) if (l[e] > l[i0]) i0 = e;
        int i1 = -1;
        for (int e = 0; e < E; e++) {
            if (e == i0) continue;
            if (i1 < 0 || l[e] > l[i1]) i1 = e;
        }
        float e1 = expf(l[i1] - l[i0]);
        float s = 1.0f + e1;
        g_tki[n * 2 + 0] = i0;  g_tkw[n * 2 + 0] = 1.0f / s;
        g_tki[n * 2 + 1] = i1;  g_tkw[n * 2 + 1] = e1 / s;
        atomicAdd(&g_cnt[i0], 1);
        atomicAdd(&g_cnt[i1], 1);
    }
}

__global__ void scan_kernel(int E) {
    if (threadIdx.x == 0) {
        int off = 0;
        for (int e = 0; e < E; e++) { g_off[e] = off; g_cur[e] = off; off += g_cnt[e]; }
    }
}

__global__ void scatter_kernel(int N) {
    int n = blockIdx.x * blockDim.x + threadIdx.x;
    if (n >= N) return;
    #pragma unroll
    for (int k = 0; k < 2; k++) {
        int e = g_tki[n * 2 + k];
        int p = atomicAdd(&g_cur[e], 1);
        g_rows[p] = n * 2 + k;
    }
}

// ================================================================ HMMA grouped GEMM
// CTA tile 128x128, K-chunk 32. 8 warps (2x4), warp tile 64x32.
// SMEM: packed A hi/lo [128][40], packed B [16][136] u32, raw B fp32 [32][132].
// Schedule: stsmem(kc) | sync | cp.async B(kc+1) + ldA(kc+1) | MMA(kc) | wait | sync.
#define APITCH   40
#define BPITCH   136
#define RAWPITCH 132

template<int STAGE>
__global__ __launch_bounds__(256, 2) void hmma_gemm(
    const float* __restrict__ Xin,     // x (stage1); unused stage2
    const float* __restrict__ Ball,    // w1 [E][D][H] / w2 [E][H][D] (native)
    const float* __restrict__ biasAll, // [E][NC]
    int K, int NC)
{
    __shared__ __half    sAh[128][APITCH];
    __shared__ __half    sAl[128][APITCH];
    __shared__ uint32_t  sBh[16][BPITCH];
    __shared__ float     rawB[32][RAWPITCH];

    int e = blockIdx.z;
    int cnt = g_cnt[e];
    int m0 = blockIdx.x * 128;           // m-tile innermost: B L2 reuse
    if (m0 >= cnt) return;
    int off = g_off[e];
    int n0 = blockIdx.y * 128;

    int tid = threadIdx.x, lane = tid & 31, wid = tid >> 5;
    int wm = wid >> 2, wn = wid & 3;      // 2 x 4 warp grid
    int gq = lane >> 2, tq = lane & 3;

    const float* Bb = Ball + (size_t)e * K * NC;

    // A staging: row = tid>>1, k-half = (tid&1)*16 floats
    int srow = tid >> 1, shalf = tid & 1;
    int arow0 = m0 + srow;
    int arcl = (arow0 < cnt) ? (off + arow0) : (off + cnt - 1);
    const float* arow;
    if (STAGE == 1) {
        int token = g_rows[arcl] >> 1;
        arow = Xin + (size_t)token * K;
    } else {
        arow = g_hidden + (size_t)arcl * K;
    }
    // B cp.async map: row = tid>>3 (0..31), col = (tid&7)*16 floats
    int crow = tid >> 3, ccol = (tid & 7) * 16;
    uint32_t rawb_dst = smem_u32(&rawB[crow][ccol]);
    // B convert map: kpair = tid>>4 (0..15), n8 = (tid&15)*8
    int bkp = tid >> 4, bn8 = (tid & 15) * 8;

    float4 rA[4];
    auto ldregA = [&](int kc) {
        const float* ap = arow + kc * 32 + shalf * 16;
        #pragma unroll
        for (int q = 0; q < 4; q++) rA[q] = *(const float4*)(ap + q * 4);
    };
    auto cpasyncB = [&](int kc) {
        const float* bp = Bb + (size_t)(kc * 32 + crow) * NC + n0 + ccol;
        #pragma unroll
        for (int q = 0; q < 4; q++)
            cpa16(rawb_dst + q * 16, bp + q * 4);
        CP_COMMIT();
    };
    auto stsmem = [&]() {
        #pragma unroll
        for (int q = 0; q < 4; q++) {
            float4 v = rA[q];
            __half h0 = __float2half_rn(v.x), h1 = __float2half_rn(v.y);
            __half h2 = __float2half_rn(v.z), h3 = __float2half_rn(v.w);
            __half l0 = __float2half_rn(v.x - __half2float(h0));
            __half l1 = __float2half_rn(v.y - __half2float(h1));
            __half l2 = __float2half_rn(v.z - __half2float(h2));
            __half l3 = __float2half_rn(v.w - __half2float(h3));
            int c = shalf * 16 + q * 4;
            *(uint2*)&sAh[srow][c] = make_uint2(packh(h0, h1), packh(h2, h3));
            *(uint2*)&sAl[srow][c] = make_uint2(packh(l0, l1), packh(l2, l3));
        }
        // B: read raw fp32 rows (2bkp, 2bkp+1), pack k-pairs per n
        float4 a0 = *(const float4*)&rawB[2 * bkp][bn8];
        float4 a1 = *(const float4*)&rawB[2 * bkp][bn8 + 4];
        float4 b0 = *(const float4*)&rawB[2 * bkp + 1][bn8];
        float4 b1 = *(const float4*)&rawB[2 * bkp + 1][bn8 + 4];
        const float* fa = (const float*)&a0;   // a0,a1 contiguous? no — handle pairs
        uint4 o0, o1;
        o0.x = packh(__float2half_rn(a0.x), __float2half_rn(b0.x));
        o0.y = packh(__float2half_rn(a0.y), __float2half_rn(b0.y));
        o0.z = packh(__float2half_rn(a0.z), __float2half_rn(b0.z));
        o0.w = packh(__float2half_rn(a0.w), __float2half_rn(b0.w));
        o1.x = packh(__float2half_rn(a1.x), __float2half_rn(b1.x));
        o1.y = packh(__float2half_rn(a1.y), __float2half_rn(b1.y));
        o1.z = packh(__float2half_rn(a1.z), __float2half_rn(b1.z));
        o1.w = packh(__float2half_rn(a1.w), __float2half_rn(b1.w));
        (void)fa;
        *(uint4*)&sBh[bkp][bn8]     = o0;
        *(uint4*)&sBh[bkp][bn8 + 4] = o1;
    };

    float acc[4][4][4];
    #pragma unroll
    for (int i = 0; i < 4; i++)
        #pragma unroll
        for (int j = 0; j < 4; j++)
            #pragma unroll
            for (int q = 0; q < 4; q++) acc[i][j][q] = 0.f;

    int KC = K / 32;
    // prime: A(0) regs + B(0) raw
    ldregA(0);
    cpasyncB(0);
    CP_WAIT0();
    __syncthreads();

    for (int kc = 0; kc < KC; kc++) {
        bool more = (kc + 1 < KC);
        stsmem();                    // convert rA(kc) + rawB(kc) -> packed
        __syncthreads();             // packed visible; rawB fully consumed
        if (more) {
            cpasyncB(kc + 1);        // B(kc+1) flies under MMA
            ldregA(kc + 1);          // A(kc+1) flies under MMA
        }

        #pragma unroll
        for (int ks = 0; ks < 2; ks++) {
            int k0 = ks * 16 + tq * 2;
            int kp = ks * 8 + tq;
            uint32_t bh[4][2];
            #pragma unroll
            for (int nt = 0; nt < 4; nt++) {
                int n = wn * 32 + nt * 8 + gq;
                bh[nt][0] = sBh[kp][n];
                bh[nt][1] = sBh[kp + 4][n];
            }
            #pragma unroll
            for (int mt = 0; mt < 4; mt++) {
                int r = wm * 64 + mt * 16 + gq;
                uint32_t ah[4], al[4];
                ah[0] = *(const uint32_t*)&sAh[r][k0];
                ah[1] = *(const uint32_t*)&sAh[r + 8][k0];
                ah[2] = *(const uint32_t*)&sAh[r][k0 + 8];
                ah[3] = *(const uint32_t*)&sAh[r + 8][k0 + 8];
                al[0] = *(const uint32_t*)&sAl[r][k0];
                al[1] = *(const uint32_t*)&sAl[r + 8][k0];
                al[2] = *(const uint32_t*)&sAl[r][k0 + 8];
                al[3] = *(const uint32_t*)&sAl[r + 8][k0 + 8];
                #pragma unroll
                for (int nt = 0; nt < 4; nt++) {
                    mma16816(acc[mt][nt], ah, bh[nt]);
                    mma16816(acc[mt][nt], al, bh[nt]);
                }
            }
        }

        if (more) CP_WAIT0();        // rawB(kc+1) landed
        __syncthreads();             // packed consumed; rawB(kc+1) visible
    }

    // epilogue: rows wm*64+mt*16+gq(+8), cols wn*32+nt*8+tq*2
    const float* bias = biasAll + (size_t)e * NC + n0;
    #pragma unroll
    for (int mt = 0; mt < 4; mt++) {
        #pragma unroll
        for (int h = 0; h < 2; h++) {
            int mg = m0 + wm * 64 + mt * 16 + gq + h * 8;
            if (mg >= cnt) continue;
            size_t prow = (size_t)off + mg;
            int drow = (STAGE == 2) ? g_rows[prow] : 0;
            #pragma unroll
            for (int nt = 0; nt < 4; nt++) {
                int colL = wn * 32 + nt * 8 + tq * 2;
                float v0 = acc[mt][nt][h * 2 + 0] + bias[colL];
                float v1 = acc[mt][nt][h * 2 + 1] + bias[colL + 1];
                if (STAGE == 1) {
                    float2 o = make_float2(gelu_exact(v0), gelu_exact(v1));
                    *(float2*)(g_hidden + prow * NC + n0 + colL) = o;
                } else {
                    float2 o = make_float2(v0, v1);
                    *(float2*)(g_ybuf + (size_t)drow * NC + n0 + colL) = o;
                }
            }
        }
    }
}

// ================================================================ combine
__global__ void combine_kernel(float* __restrict__ out, int N, int Dq) {
    int id = blockIdx.x * blockDim.x + threadIdx.x;
    if (id >= N * Dq) return;
    int n = id / Dq, d4 = id % Dq;
    float w0 = g_tkw[n * 2 + 0];
    float w1 = g_tkw[n * 2 + 1];
    const float4* y0 = (const float4*)&g_ybuf[(size_t)(n * 2 + 0) * Dq * 4];
    const float4* y1 = (const float4*)&g_ybuf[(size_t)(n * 2 + 1) * Dq * 4];
    float4 a = y0[d4], b = y1[d4];
    float4 r;
    r.x = w0 * a.x + w1 * b.x;
    r.y = w0 * a.y + w1 * b.y;
    r.z = w0 * a.z + w1 * b.z;
    r.w = w0 * a.w + w1 * b.w;
    ((float4*)out)[id] = r;
}

// ================================================================ launch
extern "C" void kernel_launch(void* const* d_in, const int* in_sizes, int n_in,
                              void* d_out, int out_size) {
    const float* x  = (const float*)d_in[0];   // [B,T,D]
    const float* gw = (const float*)d_in[1];   // [D,E]
    const float* w1 = (const float*)d_in[2];   // [E,D,H]
    const float* b1 = (const float*)d_in[3];   // [E,H]
    const float* w2 = (const float*)d_in[4];   // [E,H,D]
    const float* b2 = (const float*)d_in[5];   // [E,D]

    long s2 = in_sizes[2], s3 = in_sizes[3], s5 = in_sizes[5];
    int D = (int)(s2 / s3);
    int E = (int)(s5 / D);
    int H = (int)(s3 / E);
    int N = (int)(in_sizes[0] / D);
    int N2 = 2 * N;

    init_kernel<<<1, 32>>>(E);
    router_kernel<<<N, 128>>>(x, gw, D, E);
    scan_kernel<<<1, 32>>>(E);
    scatter_kernel<<<(N + 255) / 256, 256>>>(N);

    int MT = (N2 + 127) / 128;
    dim3 g1(MT, H / 128, E);               // m-tile innermost
    hmma_gemm<1><<<g1, 256>>>(x, w1, b1, D, H);
    dim3 g2(MT, D / 128, E);
    hmma_gemm<2><<<g2, 256>>>(x, w2, b2, H, D);

    int Dq = D / 4;
    combine_kernel<<<(N * Dq + 255) / 256, 256>>>((float*)d_out, N, Dq);
}

// round 12
// speedup vs baseline: 1.4586x; 1.4586x over previous
#include <cuda_runtime.h>
#include <cuda_fp16.h>
#include <cstdint>
#include <math.h>

// MoE FFN: router top-2 -> grouped HMMA GEMM -> combine.
// R12 = R9 with stage-2 using single-term fp16 A (stage-1 keeps 2-term hi/lo
// split). Structure otherwise identical to the best (R9) kernel.

#define MAXE      16
#define CAP_ROWS  8192
#define CAP_H     4096
#define CAP_D     1024

__device__ int   g_cnt[MAXE];
__device__ int   g_off[MAXE];
__device__ int   g_cur[MAXE];
__device__ int   g_rows[CAP_ROWS];
__device__ int   g_tki[CAP_ROWS];
__device__ float g_tkw[CAP_ROWS];
__device__ float g_hidden[(size_t)CAP_ROWS * CAP_H];  // 128 MB
__device__ float g_ybuf[(size_t)CAP_ROWS * CAP_D];    // 32 MB

// ================================================================ mma helpers
__device__ __forceinline__ void mma16816(float* c, const uint32_t* a,
                                         const uint32_t* b) {
    asm volatile(
        "mma.sync.aligned.m16n8k16.row.col.f32.f16.f16.f32 "
        "{%0,%1,%2,%3}, {%4,%5,%6,%7}, {%8,%9}, {%0,%1,%2,%3};"
        : "+f"(c[0]), "+f"(c[1]), "+f"(c[2]), "+f"(c[3])
        : "r"(a[0]), "r"(a[1]), "r"(a[2]), "r"(a[3]), "r"(b[0]), "r"(b[1]));
}
__device__ __forceinline__ uint32_t packh(__half a, __half b) {
    return (uint32_t)__half_as_ushort(a) | ((uint32_t)__half_as_ushort(b) << 16);
}
__device__ __forceinline__ float gelu_exact(float v) {
    return 0.5f * v * (1.0f + erff(v * 0.70710678118654752f));
}

// ================================================================ router chain
__global__ void init_kernel(int E) {
    if (threadIdx.x < E) g_cnt[threadIdx.x] = 0;
}

__global__ __launch_bounds__(128) void router_kernel(
    const float* __restrict__ x, const float* __restrict__ gw, int D, int E)
{
    int n = blockIdx.x, t = threadIdx.x;
    float acc[MAXE];
    #pragma unroll
    for (int e = 0; e < MAXE; e++) acc[e] = 0.f;
    const float* xr = x + (size_t)n * D;
    for (int i = t; i < D; i += 128) {
        float xv = xr[i];
        const float* g = gw + (size_t)i * E;
        for (int e = 0; e < E; e++) acc[e] += xv * g[e];
    }
    for (int e = 0; e < E; e++)
        for (int o = 16; o > 0; o >>= 1)
            acc[e] += __shfl_down_sync(0xffffffffu, acc[e], o);
    __shared__ float sred[4][MAXE];
    int warp = t >> 5, lane = t & 31;
    if (lane == 0)
        for (int e = 0; e < E; e++) sred[warp][e] = acc[e];
    __syncthreads();
    if (t == 0) {
        float l[MAXE];
        for (int e = 0; e < E; e++)
            l[e] = sred[0][e] + sred[1][e] + sred[2][e] + sred[3][e];
        int i0 = 0;
        for (int e = 1; e < E; e++) if (l[e] > l[i0]) i0 = e;
        int i1 = -1;
        for (int e = 0; e < E; e++) {
            if (e == i0) continue;
            if (i1 < 0 || l[e] > l[i1]) i1 = e;
        }
        float e1 = expf(l[i1] - l[i0]);
        float s = 1.0f + e1;
        g_tki[n * 2 + 0] = i0;  g_tkw[n * 2 + 0] = 1.0f / s;
        g_tki[n * 2 + 1] = i1;  g_tkw[n * 2 + 1] = e1 / s;
        atomicAdd(&g_cnt[i0], 1);
        atomicAdd(&g_cnt[i1], 1);
    }
}

__global__ void scan_kernel(int E) {
    if (threadIdx.x == 0) {
        int off = 0;
        for (int e = 0; e < E; e++) { g_off[e] = off; g_cur[e] = off; off += g_cnt[e]; }
    }
}

__global__ void scatter_kernel(int N) {
    int n = blockIdx.x * blockDim.x + threadIdx.x;
    if (n >= N) return;
    #pragma unroll
    for (int k = 0; k < 2; k++) {
        int e = g_tki[n * 2 + k];
        int p = atomicAdd(&g_cur[e], 1);
        g_rows[p] = n * 2 + k;
    }
}

// ================================================================ HMMA grouped GEMM
// CTA tile 128x128, K-chunk 32. 8 warps (2x4), warp tile 64x32.
// STAGE 1: 2-term split (Ah*Bh + Al*Bh). STAGE 2: single term (Ah*Bh), A fp16.
#define APITCH 40
#define BPITCH 136

template<int STAGE>
__global__ __launch_bounds__(256, 2) void hmma_gemm(
    const float* __restrict__ Xin,     // x (stage1); unused stage2
    const float* __restrict__ Ball,    // w1 [E][D][H] / w2 [E][H][D] (native)
    const float* __restrict__ biasAll, // [E][NC]
    int K, int NC)
{
    constexpr int TERMS = (STAGE == 1) ? 2 : 1;

    __shared__ __half    sAh[128][APITCH];
    __shared__ __half    sAl[(TERMS == 2) ? 128 : 1][APITCH];
    __shared__ uint32_t  sBh[16][BPITCH];

    int e = blockIdx.z;
    int cnt = g_cnt[e];
    int m0 = blockIdx.x * 128;           // m-tile innermost: B L2 reuse
    if (m0 >= cnt) return;
    int off = g_off[e];
    int n0 = blockIdx.y * 128;

    int tid = threadIdx.x, lane = tid & 31, wid = tid >> 5;
    int wm = wid >> 2, wn = wid & 3;      // 2 x 4 warp grid
    int gq = lane >> 2, tq = lane & 3;

    const float* Bb = Ball + (size_t)e * K * NC;

    // A staging: row = tid>>1, k-half = (tid&1)*16 floats
    int srow = tid >> 1, shalf = tid & 1;
    int arow0 = m0 + srow;
    int arcl = (arow0 < cnt) ? (off + arow0) : (off + cnt - 1);
    const float* arow;
    if (STAGE == 1) {
        int token = g_rows[arcl] >> 1;
        arow = Xin + (size_t)token * K;
    } else {
        arow = g_hidden + (size_t)arcl * K;
    }
    // B staging: kpair = tid>>4 (0..15), n8 = (tid&15)*8
    int bkp = tid >> 4, bn8 = (tid & 15) * 8;

    float4 rA[4];
    auto ldregA = [&](int kc) {
        const float* ap = arow + kc * 32 + shalf * 16;
        #pragma unroll
        for (int q = 0; q < 4; q++) rA[q] = *(const float4*)(ap + q * 4);
    };
    auto stsmem = [&](int kc) {
        #pragma unroll
        for (int q = 0; q < 4; q++) {
            float4 v = rA[q];
            __half h0 = __float2half_rn(v.x), h1 = __float2half_rn(v.y);
            __half h2 = __float2half_rn(v.z), h3 = __float2half_rn(v.w);
            int c = shalf * 16 + q * 4;
            *(uint2*)&sAh[srow][c] = make_uint2(packh(h0, h1), packh(h2, h3));
            if (TERMS == 2) {
                __half l0 = __float2half_rn(v.x - __half2float(h0));
                __half l1 = __float2half_rn(v.y - __half2float(h1));
                __half l2 = __float2half_rn(v.z - __half2float(h2));
                __half l3 = __float2half_rn(v.w - __half2float(h3));
                *(uint2*)&sAl[srow][c] = make_uint2(packh(l0, l1), packh(l2, l3));
            }
        }
        // B hi: pack halves (k, k+1) per n into one uint32
        const float* bp0 = Bb + (size_t)(kc * 32 + 2 * bkp) * NC + n0 + bn8;
        const float* bp1 = bp0 + NC;
        #pragma unroll
        for (int q = 0; q < 2; q++) {
            float4 a4 = *(const float4*)(bp0 + q * 4);
            float4 b4 = *(const float4*)(bp1 + q * 4);
            uint4 o;
            o.x = packh(__float2half_rn(a4.x), __float2half_rn(b4.x));
            o.y = packh(__float2half_rn(a4.y), __float2half_rn(b4.y));
            o.z = packh(__float2half_rn(a4.z), __float2half_rn(b4.z));
            o.w = packh(__float2half_rn(a4.w), __float2half_rn(b4.w));
            *(uint4*)&sBh[bkp][bn8 + q * 4] = o;
        }
    };

    float acc[4][4][4];
    #pragma unroll
    for (int i = 0; i < 4; i++)
        #pragma unroll
        for (int j = 0; j < 4; j++)
            #pragma unroll
            for (int q = 0; q < 4; q++) acc[i][j][q] = 0.f;

    int KC = K / 32;
    ldregA(0);

    for (int kc = 0; kc < KC; kc++) {
        __syncthreads();   // prior chunk consumed
        stsmem(kc);
        __syncthreads();
        if (kc + 1 < KC) ldregA(kc + 1);

        #pragma unroll
        for (int ks = 0; ks < 2; ks++) {
            int k0 = ks * 16 + tq * 2;
            int kp = ks * 8 + tq;
            uint32_t bh[4][2];
            #pragma unroll
            for (int nt = 0; nt < 4; nt++) {
                int n = wn * 32 + nt * 8 + gq;
                bh[nt][0] = sBh[kp][n];
                bh[nt][1] = sBh[kp + 4][n];
            }
            #pragma unroll
            for (int mt = 0; mt < 4; mt++) {
                int r = wm * 64 + mt * 16 + gq;
                uint32_t ah[4];
                ah[0] = *(const uint32_t*)&sAh[r][k0];
                ah[1] = *(const uint32_t*)&sAh[r + 8][k0];
                ah[2] = *(const uint32_t*)&sAh[r][k0 + 8];
                ah[3] = *(const uint32_t*)&sAh[r + 8][k0 + 8];
                if (TERMS == 2) {
                    uint32_t al[4];
                    al[0] = *(const uint32_t*)&sAl[r][k0];
                    al[1] = *(const uint32_t*)&sAl[r + 8][k0];
                    al[2] = *(const uint32_t*)&sAl[r][k0 + 8];
                    al[3] = *(const uint32_t*)&sAl[r + 8][k0 + 8];
                    #pragma unroll
                    for (int nt = 0; nt < 4; nt++) {
                        mma16816(acc[mt][nt], ah, bh[nt]);
                        mma16816(acc[mt][nt], al, bh[nt]);
                    }
                } else {
                    #pragma unroll
                    for (int nt = 0; nt < 4; nt++)
                        mma16816(acc[mt][nt], ah, bh[nt]);
                }
            }
        }
    }

    // epilogue: rows wm*64+mt*16+gq(+8), cols wn*32+nt*8+tq*2
    const float* bias = biasAll + (size_t)e * NC + n0;
    #pragma unroll
    for (int mt = 0; mt < 4; mt++) {
        #pragma unroll
        for (int h = 0; h < 2; h++) {
            int mg = m0 + wm * 64 + mt * 16 + gq + h * 8;
            if (mg >= cnt) continue;
            size_t prow = (size_t)off + mg;
            int drow = (STAGE == 2) ? g_rows[prow] : 0;
            #pragma unroll
            for (int nt = 0; nt < 4; nt++) {
                int colL = wn * 32 + nt * 8 + tq * 2;
                float v0 = acc[mt][nt][h * 2 + 0] + bias[colL];
                float v1 = acc[mt][nt][h * 2 + 1] + bias[colL + 1];
                if (STAGE == 1) {
                    float2 o = make_float2(gelu_exact(v0), gelu_exact(v1));
                    *(float2*)(g_hidden + prow * NC + n0 + colL) = o;
                } else {
                    float2 o = make_float2(v0, v1);
                    *(float2*)(g_ybuf + (size_t)drow * NC + n0 + colL) = o;
                }
            }
        }
    }
}

// ================================================================ combine
__global__ void combine_kernel(float* __restrict__ out, int N, int Dq) {
    int id = blockIdx.x * blockDim.x + threadIdx.x;
    if (id >= N * Dq) return;
    int n = id / Dq, d4 = id % Dq;
    float w0 = g_tkw[n * 2 + 0];
    float w1 = g_tkw[n * 2 + 1];
    const float4* y0 = (const float4*)&g_ybuf[(size_t)(n * 2 + 0) * Dq * 4];
    const float4* y1 = (const float4*)&g_ybuf[(size_t)(n * 2 + 1) * Dq * 4];
    float4 a = y0[d4], b = y1[d4];
    float4 r;
    r.x = w0 * a.x + w1 * b.x;
    r.y = w0 * a.y + w1 * b.y;
    r.z = w0 * a.z + w1 * b.z;
    r.w = w0 * a.w + w1 * b.w;
    ((float4*)out)[id] = r;
}

// ================================================================ launch
extern "C" void kernel_launch(void* const* d_in, const int* in_sizes, int n_in,
                              void* d_out, int out_size) {
    const float* x  = (const float*)d_in[0];   // [B,T,D]
    const float* gw = (const float*)d_in[1];   // [D,E]
    const float* w1 = (const float*)d_in[2];   // [E,D,H]
    const float* b1 = (const float*)d_in[3];   // [E,H]
    const float* w2 = (const float*)d_in[4];   // [E,H,D]
    const float* b2 = (const float*)d_in[5];   // [E,D]

    long s2 = in_sizes[2], s3 = in_sizes[3], s5 = in_sizes[5];
    int D = (int)(s2 / s3);
    int E = (int)(s5 / D);
    int H = (int)(s3 / E);
    int N = (int)(in_sizes[0] / D);
    int N2 = 2 * N;

    init_kernel<<<1, 32>>>(E);
    router_kernel<<<N, 128>>>(x, gw, D, E);
    scan_kernel<<<1, 32>>>(E);
    scatter_kernel<<<(N + 255) / 256, 256>>>(N);

    int MT = (N2 + 127) / 128;
    dim3 g1(MT, H / 128, E);               // m-tile innermost
    hmma_gemm<1><<<g1, 256>>>(x, w1, b1, D, H);
    dim3 g2(MT, D / 128, E);
    hmma_gemm<2><<<g2, 256>>>(x, w2, b2, H, D);

    int Dq = D / 4;
    combine_kernel<<<(N * Dq + 255) / 256, 256>>>((float*)d_out, N, Dq);
}

// round 13
// speedup vs baseline: 1.6468x; 1.1290x over previous
#include <cuda_runtime.h>
#include <cuda_fp16.h>
#include <cstdint>
#include <math.h>

// MoE FFN: router top-2 -> grouped HMMA GEMM -> combine.
// R13 = R12 with BOTH stages single-term pure-fp16 A (and fp16 B).
// Error budget measured across R9->R12 predicts ~4.2e-4 (gate 1e-3).

#define MAXE      16
#define CAP_ROWS  8192
#define CAP_H     4096
#define CAP_D     1024

__device__ int   g_cnt[MAXE];
__device__ int   g_off[MAXE];
__device__ int   g_cur[MAXE];
__device__ int   g_rows[CAP_ROWS];
__device__ int   g_tki[CAP_ROWS];
__device__ float g_tkw[CAP_ROWS];
__device__ float g_hidden[(size_t)CAP_ROWS * CAP_H];  // 128 MB
__device__ float g_ybuf[(size_t)CAP_ROWS * CAP_D];    // 32 MB

// ================================================================ mma helpers
__device__ __forceinline__ void mma16816(float* c, const uint32_t* a,
                                         const uint32_t* b) {
    asm volatile(
        "mma.sync.aligned.m16n8k16.row.col.f32.f16.f16.f32 "
        "{%0,%1,%2,%3}, {%4,%5,%6,%7}, {%8,%9}, {%0,%1,%2,%3};"
        : "+f"(c[0]), "+f"(c[1]), "+f"(c[2]), "+f"(c[3])
        : "r"(a[0]), "r"(a[1]), "r"(a[2]), "r"(a[3]), "r"(b[0]), "r"(b[1]));
}
__device__ __forceinline__ uint32_t packh(__half a, __half b) {
    return (uint32_t)__half_as_ushort(a) | ((uint32_t)__half_as_ushort(b) << 16);
}
__device__ __forceinline__ float gelu_exact(float v) {
    return 0.5f * v * (1.0f + erff(v * 0.70710678118654752f));
}

// ================================================================ router chain
__global__ void init_kernel(int E) {
    if (threadIdx.x < E) g_cnt[threadIdx.x] = 0;
}

__global__ __launch_bounds__(128) void router_kernel(
    const float* __restrict__ x, const float* __restrict__ gw, int D, int E)
{
    int n = blockIdx.x, t = threadIdx.x;
    float acc[MAXE];
    #pragma unroll
    for (int e = 0; e < MAXE; e++) acc[e] = 0.f;
    const float* xr = x + (size_t)n * D;
    for (int i = t; i < D; i += 128) {
        float xv = xr[i];
        const float* g = gw + (size_t)i * E;
        for (int e = 0; e < E; e++) acc[e] += xv * g[e];
    }
    for (int e = 0; e < E; e++)
        for (int o = 16; o > 0; o >>= 1)
            acc[e] += __shfl_down_sync(0xffffffffu, acc[e], o);
    __shared__ float sred[4][MAXE];
    int warp = t >> 5, lane = t & 31;
    if (lane == 0)
        for (int e = 0; e < E; e++) sred[warp][e] = acc[e];
    __syncthreads();
    if (t == 0) {
        float l[MAXE];
        for (int e = 0; e < E; e++)
            l[e] = sred[0][e] + sred[1][e] + sred[2][e] + sred[3][e];
        int i0 = 0;
        for (int e = 1; e < E; e++) if (l[e] > l[i0]) i0 = e;
        int i1 = -1;
        for (int e = 0; e < E; e++) {
            if (e == i0) continue;
            if (i1 < 0 || l[e] > l[i1]) i1 = e;
        }
        float e1 = expf(l[i1] - l[i0]);
        float s = 1.0f + e1;
        g_tki[n * 2 + 0] = i0;  g_tkw[n * 2 + 0] = 1.0f / s;
        g_tki[n * 2 + 1] = i1;  g_tkw[n * 2 + 1] = e1 / s;
        atomicAdd(&g_cnt[i0], 1);
        atomicAdd(&g_cnt[i1], 1);
    }
}

__global__ void scan_kernel(int E) {
    if (threadIdx.x == 0) {
        int off = 0;
        for (int e = 0; e < E; e++) { g_off[e] = off; g_cur[e] = off; off += g_cnt[e]; }
    }
}

__global__ void scatter_kernel(int N) {
    int n = blockIdx.x * blockDim.x + threadIdx.x;
    if (n >= N) return;
    #pragma unroll
    for (int k = 0; k < 2; k++) {
        int e = g_tki[n * 2 + k];
        int p = atomicAdd(&g_cur[e], 1);
        g_rows[p] = n * 2 + k;
    }
}

// ================================================================ HMMA grouped GEMM
// CTA tile 128x128, K-chunk 32. 8 warps (2x4), warp tile 64x32.
// Pure fp16 operands, fp32 accumulate. Single term both stages.
#define APITCH 40
#define BPITCH 136

template<int STAGE>
__global__ __launch_bounds__(256, 2) void hmma_gemm(
    const float* __restrict__ Xin,     // x (stage1); unused stage2
    const float* __restrict__ Ball,    // w1 [E][D][H] / w2 [E][H][D] (native)
    const float* __restrict__ biasAll, // [E][NC]
    int K, int NC)
{
    __shared__ __half    sAh[128][APITCH];
    __shared__ uint32_t  sBh[16][BPITCH];

    int e = blockIdx.z;
    int cnt = g_cnt[e];
    int m0 = blockIdx.x * 128;           // m-tile innermost: B L2 reuse
    if (m0 >= cnt) return;
    int off = g_off[e];
    int n0 = blockIdx.y * 128;

    int tid = threadIdx.x, lane = tid & 31, wid = tid >> 5;
    int wm = wid >> 2, wn = wid & 3;      // 2 x 4 warp grid
    int gq = lane >> 2, tq = lane & 3;

    const float* Bb = Ball + (size_t)e * K * NC;

    // A staging: row = tid>>1, k-half = (tid&1)*16 floats
    int srow = tid >> 1, shalf = tid & 1;
    int arow0 = m0 + srow;
    int arcl = (arow0 < cnt) ? (off + arow0) : (off + cnt - 1);
    const float* arow;
    if (STAGE == 1) {
        int token = g_rows[arcl] >> 1;
        arow = Xin + (size_t)token * K;
    } else {
        arow = g_hidden + (size_t)arcl * K;
    }
    // B staging: kpair = tid>>4 (0..15), n8 = (tid&15)*8
    int bkp = tid >> 4, bn8 = (tid & 15) * 8;

    float4 rA[4];
    auto ldregA = [&](int kc) {
        const float* ap = arow + kc * 32 + shalf * 16;
        #pragma unroll
        for (int q = 0; q < 4; q++) rA[q] = *(const float4*)(ap + q * 4);
    };
    auto stsmem = [&](int kc) {
        #pragma unroll
        for (int q = 0; q < 4; q++) {
            float4 v = rA[q];
            __half h0 = __float2half_rn(v.x), h1 = __float2half_rn(v.y);
            __half h2 = __float2half_rn(v.z), h3 = __float2half_rn(v.w);
            int c = shalf * 16 + q * 4;
            *(uint2*)&sAh[srow][c] = make_uint2(packh(h0, h1), packh(h2, h3));
        }
        // B: pack halves (k, k+1) per n into one uint32
        const float* bp0 = Bb + (size_t)(kc * 32 + 2 * bkp) * NC + n0 + bn8;
        const float* bp1 = bp0 + NC;
        #pragma unroll
        for (int q = 0; q < 2; q++) {
            float4 a4 = *(const float4*)(bp0 + q * 4);
            float4 b4 = *(const float4*)(bp1 + q * 4);
            uint4 o;
            o.x = packh(__float2half_rn(a4.x), __float2half_rn(b4.x));
            o.y = packh(__float2half_rn(a4.y), __float2half_rn(b4.y));
            o.z = packh(__float2half_rn(a4.z), __float2half_rn(b4.z));
            o.w = packh(__float2half_rn(a4.w), __float2half_rn(b4.w));
            *(uint4*)&sBh[bkp][bn8 + q * 4] = o;
        }
    };

    float acc[4][4][4];
    #pragma unroll
    for (int i = 0; i < 4; i++)
        #pragma unroll
        for (int j = 0; j < 4; j++)
            #pragma unroll
            for (int q = 0; q < 4; q++) acc[i][j][q] = 0.f;

    int KC = K / 32;
    ldregA(0);

    for (int kc = 0; kc < KC; kc++) {
        __syncthreads();   // prior chunk consumed
        stsmem(kc);
        __syncthreads();
        if (kc + 1 < KC) ldregA(kc + 1);

        #pragma unroll
        for (int ks = 0; ks < 2; ks++) {
            int k0 = ks * 16 + tq * 2;
            int kp = ks * 8 + tq;
            uint32_t bh[4][2];
            #pragma unroll
            for (int nt = 0; nt < 4; nt++) {
                int n = wn * 32 + nt * 8 + gq;
                bh[nt][0] = sBh[kp][n];
                bh[nt][1] = sBh[kp + 4][n];
            }
            #pragma unroll
            for (int mt = 0; mt < 4; mt++) {
                int r = wm * 64 + mt * 16 + gq;
                uint32_t ah[4];
                ah[0] = *(const uint32_t*)&sAh[r][k0];
                ah[1] = *(const uint32_t*)&sAh[r + 8][k0];
                ah[2] = *(const uint32_t*)&sAh[r][k0 + 8];
                ah[3] = *(const uint32_t*)&sAh[r + 8][k0 + 8];
                #pragma unroll
                for (int nt = 0; nt < 4; nt++)
                    mma16816(acc[mt][nt], ah, bh[nt]);
            }
        }
    }

    // epilogue: rows wm*64+mt*16+gq(+8), cols wn*32+nt*8+tq*2
    const float* bias = biasAll + (size_t)e * NC + n0;
    #pragma unroll
    for (int mt = 0; mt < 4; mt++) {
        #pragma unroll
        for (int h = 0; h < 2; h++) {
            int mg = m0 + wm * 64 + mt * 16 + gq + h * 8;
            if (mg >= cnt) continue;
            size_t prow = (size_t)off + mg;
            int drow = (STAGE == 2) ? g_rows[prow] : 0;
            #pragma unroll
            for (int nt = 0; nt < 4; nt++) {
                int colL = wn * 32 + nt * 8 + tq * 2;
                float v0 = acc[mt][nt][h * 2 + 0] + bias[colL];
                float v1 = acc[mt][nt][h * 2 + 1] + bias[colL + 1];
                if (STAGE == 1) {
                    float2 o = make_float2(gelu_exact(v0), gelu_exact(v1));
                    *(float2*)(g_hidden + prow * NC + n0 + colL) = o;
                } else {
                    float2 o = make_float2(v0, v1);
                    *(float2*)(g_ybuf + (size_t)drow * NC + n0 + colL) = o;
                }
            }
        }
    }
}

// ================================================================ combine
__global__ void combine_kernel(float* __restrict__ out, int N, int Dq) {
    int id = blockIdx.x * blockDim.x + threadIdx.x;
    if (id >= N * Dq) return;
    int n = id / Dq, d4 = id % Dq;
    float w0 = g_tkw[n * 2 + 0];
    float w1 = g_tkw[n * 2 + 1];
    const float4* y0 = (const float4*)&g_ybuf[(size_t)(n * 2 + 0) * Dq * 4];
    const float4* y1 = (const float4*)&g_ybuf[(size_t)(n * 2 + 1) * Dq * 4];
    float4 a = y0[d4], b = y1[d4];
    float4 r;
    r.x = w0 * a.x + w1 * b.x;
    r.y = w0 * a.y + w1 * b.y;
    r.z = w0 * a.z + w1 * b.z;
    r.w = w0 * a.w + w1 * b.w;
    ((float4*)out)[id] = r;
}

// ================================================================ launch
extern "C" void kernel_launch(void* const* d_in, const int* in_sizes, int n_in,
                              void* d_out, int out_size) {
    const float* x  = (const float*)d_in[0];   // [B,T,D]
    const float* gw = (const float*)d_in[1];   // [D,E]
    const float* w1 = (const float*)d_in[2];   // [E,D,H]
    const float* b1 = (const float*)d_in[3];   // [E,H]
    const float* w2 = (const float*)d_in[4];   // [E,H,D]
    const float* b2 = (const float*)d_in[5];   // [E,D]

    long s2 = in_sizes[2], s3 = in_sizes[3], s5 = in_sizes[5];
    int D = (int)(s2 / s3);
    int E = (int)(s5 / D);
    int H = (int)(s3 / E);
    int N = (int)(in_sizes[0] / D);
    int N2 = 2 * N;

    init_kernel<<<1, 32>>>(E);
    router_kernel<<<N, 128>>>(x, gw, D, E);
    scan_kernel<<<1, 32>>>(E);
    scatter_kernel<<<(N + 255) / 256, 256>>>(N);

    int MT = (N2 + 127) / 128;
    dim3 g1(MT, H / 128, E);               // m-tile innermost
    hmma_gemm<1><<<g1, 256>>>(x, w1, b1, D, H);
    dim3 g2(MT, D / 128, E);
    hmma_gemm<2><<<g2, 256>>>(x, w2, b2, H, D);

    int Dq = D / 4;
    combine_kernel<<<(N * Dq + 255) / 256, 256>>>((float*)d_out, N, Dq);
}

// round 15
// speedup vs baseline: 1.7669x; 1.0729x over previous
#include <cuda_runtime.h>
#include <cuda_fp16.h>
#include <cstdint>
#include <math.h>

// MoE FFN: router top-2 -> grouped HMMA GEMM -> combine.
// R15 = R14 with the stage-2 A register load fixed (2 x uint4 = 16 halfs).
// fp16 g_hidden (bit-identical to R13 math) + double-buffered SMEM,
// one sync per chunk, 37.9KB/CTA -> 2 CTAs/SM.

#define MAXE      16
#define CAP_ROWS  8192
#define CAP_H     4096
#define CAP_D     1024

__device__ int    g_cnt[MAXE];
__device__ int    g_off[MAXE];
__device__ int    g_cur[MAXE];
__device__ int    g_rows[CAP_ROWS];
__device__ int    g_tki[CAP_ROWS];
__device__ float  g_tkw[CAP_ROWS];
__device__ __half g_hidden16[(size_t)CAP_ROWS * CAP_H];  // 64 MB
__device__ float  g_ybuf[(size_t)CAP_ROWS * CAP_D];      // 32 MB

// ================================================================ mma helpers
__device__ __forceinline__ void mma16816(float* c, const uint32_t* a,
                                         const uint32_t* b) {
    asm volatile(
        "mma.sync.aligned.m16n8k16.row.col.f32.f16.f16.f32 "
        "{%0,%1,%2,%3}, {%4,%5,%6,%7}, {%8,%9}, {%0,%1,%2,%3};"
        : "+f"(c[0]), "+f"(c[1]), "+f"(c[2]), "+f"(c[3])
        : "r"(a[0]), "r"(a[1]), "r"(a[2]), "r"(a[3]), "r"(b[0]), "r"(b[1]));
}
__device__ __forceinline__ uint32_t packh(__half a, __half b) {
    return (uint32_t)__half_as_ushort(a) | ((uint32_t)__half_as_ushort(b) << 16);
}
__device__ __forceinline__ float gelu_exact(float v) {
    return 0.5f * v * (1.0f + erff(v * 0.70710678118654752f));
}

// ================================================================ router chain
__global__ void init_kernel(int E) {
    if (threadIdx.x < E) g_cnt[threadIdx.x] = 0;
}

__global__ __launch_bounds__(128) void router_kernel(
    const float* __restrict__ x, const float* __restrict__ gw, int D, int E)
{
    int n = blockIdx.x, t = threadIdx.x;
    float acc[MAXE];
    #pragma unroll
    for (int e = 0; e < MAXE; e++) acc[e] = 0.f;
    const float* xr = x + (size_t)n * D;
    for (int i = t; i < D; i += 128) {
        float xv = xr[i];
        const float* g = gw + (size_t)i * E;
        for (int e = 0; e < E; e++) acc[e] += xv * g[e];
    }
    for (int e = 0; e < E; e++)
        for (int o = 16; o > 0; o >>= 1)
            acc[e] += __shfl_down_sync(0xffffffffu, acc[e], o);
    __shared__ float sred[4][MAXE];
    int warp = t >> 5, lane = t & 31;
    if (lane == 0)
        for (int e = 0; e < E; e++) sred[warp][e] = acc[e];
    __syncthreads();
    if (t == 0) {
        float l[MAXE];
        for (int e = 0; e < E; e++)
            l[e] = sred[0][e] + sred[1][e] + sred[2][e] + sred[3][e];
        int i0 = 0;
        for (int e = 1; e < E; e++) if (l[e] > l[i0]) i0 = e;
        int i1 = -1;
        for (int e = 0; e < E; e++) {
            if (e == i0) continue;
            if (i1 < 0 || l[e] > l[i1]) i1 = e;
        }
        float e1 = expf(l[i1] - l[i0]);
        float s = 1.0f + e1;
        g_tki[n * 2 + 0] = i0;  g_tkw[n * 2 + 0] = 1.0f / s;
        g_tki[n * 2 + 1] = i1;  g_tkw[n * 2 + 1] = e1 / s;
        atomicAdd(&g_cnt[i0], 1);
        atomicAdd(&g_cnt[i1], 1);
    }
}

__global__ void scan_kernel(int E) {
    if (threadIdx.x == 0) {
        int off = 0;
        for (int e = 0; e < E; e++) { g_off[e] = off; g_cur[e] = off; off += g_cnt[e]; }
    }
}

__global__ void scatter_kernel(int N) {
    int n = blockIdx.x * blockDim.x + threadIdx.x;
    if (n >= N) return;
    #pragma unroll
    for (int k = 0; k < 2; k++) {
        int e = g_tki[n * 2 + k];
        int p = atomicAdd(&g_cur[e], 1);
        g_rows[p] = n * 2 + k;
    }
}

// ================================================================ HMMA grouped GEMM
// CTA tile 128x128, K-chunk 32. 8 warps (2x4), warp tile 64x32.
// Double-buffered: sAh[2][128][40] fp16, sBh[2][16][136] u32 k-pair packed.
// One __syncthreads per chunk: ld(kc+1) | MMA(kc) | st(kc+1 -> other buf) | sync.
#define APITCH 40
#define BPITCH 136

template<int STAGE>
__global__ __launch_bounds__(256, 2) void hmma_gemm(
    const float* __restrict__ Xin,     // x (stage1); unused stage2
    const float* __restrict__ Ball,    // w1 [E][D][H] / w2 [E][H][D] (native)
    const float* __restrict__ biasAll, // [E][NC]
    int K, int NC)
{
    __shared__ __half    sAh[2][128][APITCH];
    __shared__ uint32_t  sBh[2][16][BPITCH];

    int e = blockIdx.z;
    int cnt = g_cnt[e];
    int m0 = blockIdx.x * 128;           // m-tile innermost: B L2 reuse
    if (m0 >= cnt) return;
    int off = g_off[e];
    int n0 = blockIdx.y * 128;

    int tid = threadIdx.x, lane = tid & 31, wid = tid >> 5;
    int wm = wid >> 2, wn = wid & 3;      // 2 x 4 warp grid
    int gq = lane >> 2, tq = lane & 3;

    const float* Bb = Ball + (size_t)e * K * NC;

    // A staging: row = tid>>1, k-half = (tid&1)*16 elements
    int srow = tid >> 1, shalf = tid & 1;
    int arow0 = m0 + srow;
    int arcl = (arow0 < cnt) ? (off + arow0) : (off + cnt - 1);
    const float*  arow32 = nullptr;
    const __half* arow16 = nullptr;
    if (STAGE == 1) {
        int token = g_rows[arcl] >> 1;
        arow32 = Xin + (size_t)token * K;
    } else {
        arow16 = g_hidden16 + (size_t)arcl * K;
    }
    // B staging: kpair = tid>>4 (0..15), n8 = (tid&15)*8
    int bkp = tid >> 4, bn8 = (tid & 15) * 8;

    float4 rA32[4];        // stage 1: 16 floats
    uint4  rA16[2];        // stage 2: 16 halfs = 32 B = 2 x uint4
    float4 rB0[2], rB1[2];

    auto ldreg = [&](int kc) {
        if (STAGE == 1) {
            const float* ap = arow32 + kc * 32 + shalf * 16;
            #pragma unroll
            for (int q = 0; q < 4; q++) rA32[q] = *(const float4*)(ap + q * 4);
        } else {
            const __half* ap = arow16 + kc * 32 + shalf * 16;
            rA16[0] = *(const uint4*)(ap);
            rA16[1] = *(const uint4*)(ap + 8);
        }
        const float* bp0 = Bb + (size_t)(kc * 32 + 2 * bkp) * NC + n0 + bn8;
        const float* bp1 = bp0 + NC;
        #pragma unroll
        for (int q = 0; q < 2; q++) {
            rB0[q] = *(const float4*)(bp0 + q * 4);
            rB1[q] = *(const float4*)(bp1 + q * 4);
        }
    };
    auto stsmem = [&](int s) {
        if (STAGE == 1) {
            #pragma unroll
            for (int q = 0; q < 4; q++) {
                float4 v = rA32[q];
                __half h0 = __float2half_rn(v.x), h1 = __float2half_rn(v.y);
                __half h2 = __float2half_rn(v.z), h3 = __float2half_rn(v.w);
                int c = shalf * 16 + q * 4;
                *(uint2*)&sAh[s][srow][c] =
                    make_uint2(packh(h0, h1), packh(h2, h3));
            }
        } else {
            int c = shalf * 16;
            *(uint4*)&sAh[s][srow][c]     = rA16[0];
            *(uint4*)&sAh[s][srow][c + 8] = rA16[1];
        }
        const float* f0 = (const float*)rB0;
        const float* f1 = (const float*)rB1;
        uint32_t bhp[8];
        #pragma unroll
        for (int j = 0; j < 8; j++)
            bhp[j] = packh(__float2half_rn(f0[j]), __float2half_rn(f1[j]));
        *(uint4*)&sBh[s][bkp][bn8]     = *(uint4*)&bhp[0];
        *(uint4*)&sBh[s][bkp][bn8 + 4] = *(uint4*)&bhp[4];
    };

    float acc[4][4][4];
    #pragma unroll
    for (int i = 0; i < 4; i++)
        #pragma unroll
        for (int j = 0; j < 4; j++)
            #pragma unroll
            for (int q = 0; q < 4; q++) acc[i][j][q] = 0.f;

    int KC = K / 32;
    ldreg(0);
    stsmem(0);
    __syncthreads();

    for (int kc = 0; kc < KC; kc++) {
        int s = kc & 1;
        bool more = (kc + 1 < KC);
        if (more) ldreg(kc + 1);       // global loads fly under MMA

        #pragma unroll
        for (int ks = 0; ks < 2; ks++) {
            int k0 = ks * 16 + tq * 2;
            int kp = ks * 8 + tq;
            uint32_t bh[4][2];
            #pragma unroll
            for (int nt = 0; nt < 4; nt++) {
                int n = wn * 32 + nt * 8 + gq;
                bh[nt][0] = sBh[s][kp][n];
                bh[nt][1] = sBh[s][kp + 4][n];
            }
            #pragma unroll
            for (int mt = 0; mt < 4; mt++) {
                int r = wm * 64 + mt * 16 + gq;
                uint32_t ah[4];
                ah[0] = *(const uint32_t*)&sAh[s][r][k0];
                ah[1] = *(const uint32_t*)&sAh[s][r + 8][k0];
                ah[2] = *(const uint32_t*)&sAh[s][r][k0 + 8];
                ah[3] = *(const uint32_t*)&sAh[s][r + 8][k0 + 8];
                #pragma unroll
                for (int nt = 0; nt < 4; nt++)
                    mma16816(acc[mt][nt], ah, bh[nt]);
            }
        }

        if (more) stsmem(s ^ 1);       // fill other buffer
        __syncthreads();
    }

    // epilogue: rows wm*64+mt*16+gq(+8), cols wn*32+nt*8+tq*2
    const float* bias = biasAll + (size_t)e * NC + n0;
    #pragma unroll
    for (int mt = 0; mt < 4; mt++) {
        #pragma unroll
        for (int h = 0; h < 2; h++) {
            int mg = m0 + wm * 64 + mt * 16 + gq + h * 8;
            if (mg >= cnt) continue;
            size_t prow = (size_t)off + mg;
            int drow = (STAGE == 2) ? g_rows[prow] : 0;
            #pragma unroll
            for (int nt = 0; nt < 4; nt++) {
                int colL = wn * 32 + nt * 8 + tq * 2;
                float v0 = acc[mt][nt][h * 2 + 0] + bias[colL];
                float v1 = acc[mt][nt][h * 2 + 1] + bias[colL + 1];
                if (STAGE == 1) {
                    // fp16 gelu store: exactly the value stage-2 consumed in R13
                    __half g0 = __float2half_rn(gelu_exact(v0));
                    __half g1 = __float2half_rn(gelu_exact(v1));
                    *(uint32_t*)(g_hidden16 + prow * NC + n0 + colL) = packh(g0, g1);
                } else {
                    float2 o = make_float2(v0, v1);
                    *(float2*)(g_ybuf + (size_t)drow * NC + n0 + colL) = o;
                }
            }
        }
    }
}

// ================================================================ combine
__global__ void combine_kernel(float* __restrict__ out, int N, int Dq) {
    int id = blockIdx.x * blockDim.x + threadIdx.x;
    if (id >= N * Dq) return;
    int n = id / Dq, d4 = id % Dq;
    float w0 = g_tkw[n * 2 + 0];
    float w1 = g_tkw[n * 2 + 1];
    const float4* y0 = (const float4*)&g_ybuf[(size_t)(n * 2 + 0) * Dq * 4];
    const float4* y1 = (const float4*)&g_ybuf[(size_t)(n * 2 + 1) * Dq * 4];
    float4 a = y0[d4], b = y1[d4];
    float4 r;
    r.x = w0 * a.x + w1 * b.x;
    r.y = w0 * a.y + w1 * b.y;
    r.z = w0 * a.z + w1 * b.z;
    r.w = w0 * a.w + w1 * b.w;
    ((float4*)out)[id] = r;
}

// ================================================================ launch
extern "C" void kernel_launch(void* const* d_in, const int* in_sizes, int n_in,
                              void* d_out, int out_size) {
    const float* x  = (const float*)d_in[0];   // [B,T,D]
    const float* gw = (const float*)d_in[1];   // [D,E]
    const float* w1 = (const float*)d_in[2];   // [E,D,H]
    const float* b1 = (const float*)d_in[3];   // [E,H]
    const float* w2 = (const float*)d_in[4];   // [E,H,D]
    const float* b2 = (const float*)d_in[5];   // [E,D]

    long s2 = in_sizes[2], s3 = in_sizes[3], s5 = in_sizes[5];
    int D = (int)(s2 / s3);
    int E = (int)(s5 / D);
    int H = (int)(s3 / E);
    int N = (int)(in_sizes[0] / D);
    int N2 = 2 * N;

    init_kernel<<<1, 32>>>(E);
    router_kernel<<<N, 128>>>(x, gw, D, E);
    scan_kernel<<<1, 32>>>(E);
    scatter_kernel<<<(N + 255) / 256, 256>>>(N);

    int MT = (N2 + 127) / 128;
    dim3 g1(MT, H / 128, E);               // m-tile innermost
    hmma_gemm<1><<<g1, 256>>>(x, w1, b1, D, H);
    dim3 g2(MT, D / 128, E);
    hmma_gemm<2><<<g2, 256>>>(x, w2, b2, H, D);

    int Dq = D / 4;
    combine_kernel<<<(N * Dq + 255) / 256, 256>>>((float*)d_out, N, Dq);
}

// round 16
// speedup vs baseline: 1.9974x; 1.1305x over previous
#include <cuda_runtime.h>
#include <cuda_fp16.h>
#include <cstdint>
#include <math.h>

// MoE FFN: router top-2 -> grouped HMMA GEMM -> combine.
// R16 = R15 + ldmatrix.x4 for A fragments (8 LDSM vs 32 LDS.32 per warp/chunk)
// + paired f32x2->f16x2 conversions. Same math, less issue pressure.

#define MAXE      16
#define CAP_ROWS  8192
#define CAP_H     4096
#define CAP_D     1024

__device__ int    g_cnt[MAXE];
__device__ int    g_off[MAXE];
__device__ int    g_cur[MAXE];
__device__ int    g_rows[CAP_ROWS];
__device__ int    g_tki[CAP_ROWS];
__device__ float  g_tkw[CAP_ROWS];
__device__ __half g_hidden16[(size_t)CAP_ROWS * CAP_H];  // 64 MB
__device__ float  g_ybuf[(size_t)CAP_ROWS * CAP_D];      // 32 MB

// ================================================================ helpers
__device__ __forceinline__ void mma16816(float* c, const uint32_t* a,
                                         const uint32_t* b) {
    asm volatile(
        "mma.sync.aligned.m16n8k16.row.col.f32.f16.f16.f32 "
        "{%0,%1,%2,%3}, {%4,%5,%6,%7}, {%8,%9}, {%0,%1,%2,%3};"
        : "+f"(c[0]), "+f"(c[1]), "+f"(c[2]), "+f"(c[3])
        : "r"(a[0]), "r"(a[1]), "r"(a[2]), "r"(a[3]), "r"(b[0]), "r"(b[1]));
}
__device__ __forceinline__ void ldm_x4(uint32_t& r0, uint32_t& r1,
                                       uint32_t& r2, uint32_t& r3, uint32_t a) {
    asm volatile("ldmatrix.sync.aligned.m8n8.x4.shared.b16 {%0,%1,%2,%3}, [%4];"
        : "=r"(r0), "=r"(r1), "=r"(r2), "=r"(r3) : "r"(a) : "memory");
}
__device__ __forceinline__ uint32_t smem_u32(const void* p) {
    uint32_t a;
    asm("{ .reg .u64 t; cvta.to.shared.u64 t, %1; cvt.u32.u64 %0, t; }"
        : "=r"(a) : "l"(p));
    return a;
}
__device__ __forceinline__ uint32_t cvt2(float a, float b) {
    __half2 h = __float22half2_rn(make_float2(a, b));   // .x=a (lo), .y=b (hi)
    return *(uint32_t*)&h;
}
__device__ __forceinline__ uint32_t packh(__half a, __half b) {
    return (uint32_t)__half_as_ushort(a) | ((uint32_t)__half_as_ushort(b) << 16);
}
__device__ __forceinline__ float gelu_exact(float v) {
    return 0.5f * v * (1.0f + erff(v * 0.70710678118654752f));
}

// ================================================================ router chain
__global__ void init_kernel(int E) {
    if (threadIdx.x < E) g_cnt[threadIdx.x] = 0;
}

__global__ __launch_bounds__(128) void router_kernel(
    const float* __restrict__ x, const float* __restrict__ gw, int D, int E)
{
    int n = blockIdx.x, t = threadIdx.x;
    float acc[MAXE];
    #pragma unroll
    for (int e = 0; e < MAXE; e++) acc[e] = 0.f;
    const float* xr = x + (size_t)n * D;
    for (int i = t; i < D; i += 128) {
        float xv = xr[i];
        const float* g = gw + (size_t)i * E;
        for (int e = 0; e < E; e++) acc[e] += xv * g[e];
    }
    for (int e = 0; e < E; e++)
        for (int o = 16; o > 0; o >>= 1)
            acc[e] += __shfl_down_sync(0xffffffffu, acc[e], o);
    __shared__ float sred[4][MAXE];
    int warp = t >> 5, lane = t & 31;
    if (lane == 0)
        for (int e = 0; e < E; e++) sred[warp][e] = acc[e];
    __syncthreads();
    if (t == 0) {
        float l[MAXE];
        for (int e = 0; e < E; e++)
            l[e] = sred[0][e] + sred[1][e] + sred[2][e] + sred[3][e];
        int i0 = 0;
        for (int e = 1; e < E; e++) if (l[e] > l[i0]) i0 = e;
        int i1 = -1;
        for (int e = 0; e < E; e++) {
            if (e == i0) continue;
            if (i1 < 0 || l[e] > l[i1]) i1 = e;
        }
        float e1 = expf(l[i1] - l[i0]);
        float s = 1.0f + e1;
        g_tki[n * 2 + 0] = i0;  g_tkw[n * 2 + 0] = 1.0f / s;
        g_tki[n * 2 + 1] = i1;  g_tkw[n * 2 + 1] = e1 / s;
        atomicAdd(&g_cnt[i0], 1);
        atomicAdd(&g_cnt[i1], 1);
    }
}

__global__ void scan_kernel(int E) {
    if (threadIdx.x == 0) {
        int off = 0;
        for (int e = 0; e < E; e++) { g_off[e] = off; g_cur[e] = off; off += g_cnt[e]; }
    }
}

__global__ void scatter_kernel(int N) {
    int n = blockIdx.x * blockDim.x + threadIdx.x;
    if (n >= N) return;
    #pragma unroll
    for (int k = 0; k < 2; k++) {
        int e = g_tki[n * 2 + k];
        int p = atomicAdd(&g_cur[e], 1);
        g_rows[p] = n * 2 + k;
    }
}

// ================================================================ HMMA grouped GEMM
// CTA tile 128x128, K-chunk 32. 8 warps (2x4), warp tile 64x32.
// Double-buffered: sAh[2][128][40] fp16, sBh[2][16][136] u32 k-pair packed.
// A fragments via ldmatrix.x4 (pitch-40 rows -> conflict-free LDSM).
#define APITCH 40
#define BPITCH 136

template<int STAGE>
__global__ __launch_bounds__(256, 2) void hmma_gemm(
    const float* __restrict__ Xin,     // x (stage1); unused stage2
    const float* __restrict__ Ball,    // w1 [E][D][H] / w2 [E][H][D] (native)
    const float* __restrict__ biasAll, // [E][NC]
    int K, int NC)
{
    __shared__ __half    sAh[2][128][APITCH];
    __shared__ uint32_t  sBh[2][16][BPITCH];

    int e = blockIdx.z;
    int cnt = g_cnt[e];
    int m0 = blockIdx.x * 128;           // m-tile innermost: B L2 reuse
    if (m0 >= cnt) return;
    int off = g_off[e];
    int n0 = blockIdx.y * 128;

    int tid = threadIdx.x, lane = tid & 31, wid = tid >> 5;
    int wm = wid >> 2, wn = wid & 3;      // 2 x 4 warp grid
    int gq = lane >> 2, tq = lane & 3;

    const float* Bb = Ball + (size_t)e * K * NC;

    // ldmatrix A addressing (per lane): row = r_base + (lane&15), koff = ((lane>>4)&1)*8
    uint32_t sA_base[2] = { smem_u32(&sAh[0][0][0]), smem_u32(&sAh[1][0][0]) };
    int a_lrow = lane & 15;
    int a_koff = ((lane >> 4) & 1) * 8;

    // A staging: row = tid>>1, k-half = (tid&1)*16 elements
    int srow = tid >> 1, shalf = tid & 1;
    int arow0 = m0 + srow;
    int arcl = (arow0 < cnt) ? (off + arow0) : (off + cnt - 1);
    const float*  arow32 = nullptr;
    const __half* arow16 = nullptr;
    if (STAGE == 1) {
        int token = g_rows[arcl] >> 1;
        arow32 = Xin + (size_t)token * K;
    } else {
        arow16 = g_hidden16 + (size_t)arcl * K;
    }
    // B staging: kpair = tid>>4 (0..15), n8 = (tid&15)*8
    int bkp = tid >> 4, bn8 = (tid & 15) * 8;

    float4 rA32[4];        // stage 1: 16 floats
    uint4  rA16[2];        // stage 2: 16 halfs
    float4 rB0[2], rB1[2];

    auto ldreg = [&](int kc) {
        if (STAGE == 1) {
            const float* ap = arow32 + kc * 32 + shalf * 16;
            #pragma unroll
            for (int q = 0; q < 4; q++) rA32[q] = *(const float4*)(ap + q * 4);
        } else {
            const __half* ap = arow16 + kc * 32 + shalf * 16;
            rA16[0] = *(const uint4*)(ap);
            rA16[1] = *(const uint4*)(ap + 8);
        }
        const float* bp0 = Bb + (size_t)(kc * 32 + 2 * bkp) * NC + n0 + bn8;
        const float* bp1 = bp0 + NC;
        #pragma unroll
        for (int q = 0; q < 2; q++) {
            rB0[q] = *(const float4*)(bp0 + q * 4);
            rB1[q] = *(const float4*)(bp1 + q * 4);
        }
    };
    auto stsmem = [&](int s) {
        if (STAGE == 1) {
            #pragma unroll
            for (int q = 0; q < 4; q++) {
                float4 v = rA32[q];
                int c = shalf * 16 + q * 4;
                *(uint2*)&sAh[s][srow][c] =
                    make_uint2(cvt2(v.x, v.y), cvt2(v.z, v.w));
            }
        } else {
            int c = shalf * 16;
            *(uint4*)&sAh[s][srow][c]     = rA16[0];
            *(uint4*)&sAh[s][srow][c + 8] = rA16[1];
        }
        const float* f0 = (const float*)rB0;
        const float* f1 = (const float*)rB1;
        uint32_t bhp[8];
        #pragma unroll
        for (int j = 0; j < 8; j++)
            bhp[j] = cvt2(f0[j], f1[j]);
        *(uint4*)&sBh[s][bkp][bn8]     = *(uint4*)&bhp[0];
        *(uint4*)&sBh[s][bkp][bn8 + 4] = *(uint4*)&bhp[4];
    };

    float acc[4][4][4];
    #pragma unroll
    for (int i = 0; i < 4; i++)
        #pragma unroll
        for (int j = 0; j < 4; j++)
            #pragma unroll
            for (int q = 0; q < 4; q++) acc[i][j][q] = 0.f;

    int KC = K / 32;
    ldreg(0);
    stsmem(0);
    __syncthreads();

    for (int kc = 0; kc < KC; kc++) {
        int s = kc & 1;
        bool more = (kc + 1 < KC);
        if (more) ldreg(kc + 1);       // global loads fly under MMA

        #pragma unroll
        for (int ks = 0; ks < 2; ks++) {
            int k0 = ks * 16 + tq * 2;
            int kp = ks * 8 + tq;
            uint32_t bh[4][2];
            #pragma unroll
            for (int nt = 0; nt < 4; nt++) {
                int n = wn * 32 + nt * 8 + gq;
                bh[nt][0] = sBh[s][kp][n];
                bh[nt][1] = sBh[s][kp + 4][n];
            }
            #pragma unroll
            for (int mt = 0; mt < 4; mt++) {
                int r_base = wm * 64 + mt * 16;
                uint32_t ad = sA_base[s] +
                    (uint32_t)(((r_base + a_lrow) * APITCH + ks * 16 + a_koff) * 2);
                uint32_t ah[4];
                ldm_x4(ah[0], ah[1], ah[2], ah[3], ad);
                #pragma unroll
                for (int nt = 0; nt < 4; nt++)
                    mma16816(acc[mt][nt], ah, bh[nt]);
            }
        }

        if (more) stsmem(s ^ 1);       // fill other buffer
        __syncthreads();
    }

    // epilogue: rows wm*64+mt*16+gq(+8), cols wn*32+nt*8+tq*2
    const float* bias = biasAll + (size_t)e * NC + n0;
    #pragma unroll
    for (int mt = 0; mt < 4; mt++) {
        #pragma unroll
        for (int h = 0; h < 2; h++) {
            int mg = m0 + wm * 64 + mt * 16 + gq + h * 8;
            if (mg >= cnt) continue;
            size_t prow = (size_t)off + mg;
            int drow = (STAGE == 2) ? g_rows[prow] : 0;
            #pragma unroll
            for (int nt = 0; nt < 4; nt++) {
                int colL = wn * 32 + nt * 8 + tq * 2;
                float v0 = acc[mt][nt][h * 2 + 0] + bias[colL];
                float v1 = acc[mt][nt][h * 2 + 1] + bias[colL + 1];
                if (STAGE == 1) {
                    __half g0 = __float2half_rn(gelu_exact(v0));
                    __half g1 = __float2half_rn(gelu_exact(v1));
                    *(uint32_t*)(g_hidden16 + prow * NC + n0 + colL) = packh(g0, g1);
                } else {
                    float2 o = make_float2(v0, v1);
                    *(float2*)(g_ybuf + (size_t)drow * NC + n0 + colL) = o;
                }
            }
        }
    }
}

// ================================================================ combine
__global__ void combine_kernel(float* __restrict__ out, int N, int Dq) {
    int id = blockIdx.x * blockDim.x + threadIdx.x;
    if (id >= N * Dq) return;
    int n = id / Dq, d4 = id % Dq;
    float w0 = g_tkw[n * 2 + 0];
    float w1 = g_tkw[n * 2 + 1];
    const float4* y0 = (const float4*)&g_ybuf[(size_t)(n * 2 + 0) * Dq * 4];
    const float4* y1 = (const float4*)&g_ybuf[(size_t)(n * 2 + 1) * Dq * 4];
    float4 a = y0[d4], b = y1[d4];
    float4 r;
    r.x = w0 * a.x + w1 * b.x;
    r.y = w0 * a.y + w1 * b.y;
    r.z = w0 * a.z + w1 * b.z;
    r.w = w0 * a.w + w1 * b.w;
    ((float4*)out)[id] = r;
}

// ================================================================ launch
extern "C" void kernel_launch(void* const* d_in, const int* in_sizes, int n_in,
                              void* d_out, int out_size) {
    const float* x  = (const float*)d_in[0];   // [B,T,D]
    const float* gw = (const float*)d_in[1];   // [D,E]
    const float* w1 = (const float*)d_in[2];   // [E,D,H]
    const float* b1 = (const float*)d_in[3];   // [E,H]
    const float* w2 = (const float*)d_in[4];   // [E,H,D]
    const float* b2 = (const float*)d_in[5];   // [E,D]

    long s2 = in_sizes[2], s3 = in_sizes[3], s5 = in_sizes[5];
    int D = (int)(s2 / s3);
    int E = (int)(s5 / D);
    int H = (int)(s3 / E);
    int N = (int)(in_sizes[0] / D);
    int N2 = 2 * N;

    init_kernel<<<1, 32>>>(E);
    router_kernel<<<N, 128>>>(x, gw, D, E);
    scan_kernel<<<1, 32>>>(E);
    scatter_kernel<<<(N + 255) / 256, 256>>>(N);

    int MT = (N2 + 127) / 128;
    dim3 g1(MT, H / 128, E);               // m-tile innermost
    hmma_gemm<1><<<g1, 256>>>(x, w1, b1, D, H);
    dim3 g2(MT, D / 128, E);
    hmma_gemm<2><<<g2, 256>>>(x, w2, b2, H, D);

    int Dq = D / 4;
    combine_kernel<<<(N * Dq + 255) / 256, 256>>>((float*)d_out, N, Dq);
}